// round 8
// baseline (speedup 1.0000x reference)
#include <cuda_runtime.h>
#include <cuda_bf16.h>
#include <cuda_fp16.h>
#include <math.h>
#include <stdint.h>

#define N_NODES 100000
#define NPAD    100096
#define N_EDGES 3200000
#define NP1     100001
#define NSCAN_BLOCKS 98

#define WT_TILE_BYTES 65536            // packed B tile: 16 nb x 8 ks x 512B
#define PLANE_BYTES   ((size_t)NPAD * 256)   // hi plane size; lo at +PLANE_BYTES

// ======================= device scratch =======================
__device__ int    g_rowptr[NP1];
__device__ int    g_bsum[128];
__device__ int    g_pos[N_NODES];
__device__ int    g_ecol[N_EDGES];
__device__ float  g_eval[N_EDGES];
__device__ float  g_h0[(size_t)NPAD * 128];   // split act buffer A (hi|lo planes)
__device__ float  g_h1[(size_t)NPAD * 128];   // split act buffer B
__device__ __half g_supn[(size_t)NPAD * 128];
__device__ float  g_self[(size_t)NPAD * 128];
__device__ __nv_bfloat16 g_wt[9 * 32768];

// ======================= helpers =======================
__device__ __forceinline__ void mma_bf16(float* c, const unsigned* a, unsigned b0, unsigned b1) {
    asm volatile("mma.sync.aligned.m16n8k16.row.col.f32.bf16.bf16.f32 "
        "{%0,%1,%2,%3}, {%4,%5,%6,%7}, {%8,%9}, {%0,%1,%2,%3};"
        : "+f"(c[0]), "+f"(c[1]), "+f"(c[2]), "+f"(c[3])
        : "r"(a[0]), "r"(a[1]), "r"(a[2]), "r"(a[3]), "r"(b0), "r"(b1));
}
__device__ __forceinline__ unsigned pk(float a, float b) {
    __nv_bfloat162 h = __floats2bfloat162_rn(a, b);
    return *(unsigned*)&h;
}
// split v into hi/lo bf16 pairs
__device__ __forceinline__ void split4(const float* v, unsigned& h01, unsigned& h23,
                                       unsigned& l01, unsigned& l23) {
    __nv_bfloat16 h0 = __float2bfloat16_rn(v[0]);
    __nv_bfloat16 h1 = __float2bfloat16_rn(v[1]);
    __nv_bfloat16 h2 = __float2bfloat16_rn(v[2]);
    __nv_bfloat16 h3 = __float2bfloat16_rn(v[3]);
    h01 = pk(__bfloat162float(h0), __bfloat162float(h1));  // exact pack
    h23 = pk(__bfloat162float(h2), __bfloat162float(h3));
    l01 = pk(v[0] - __bfloat162float(h0), v[1] - __bfloat162float(h1));
    l23 = pk(v[2] - __bfloat162float(h2), v[3] - __bfloat162float(h3));
}

// row-warp split store: lane owns k = 4*lane..4*lane+3 of row R; v[4] values
__device__ __forceinline__ void split_store_row(char* plane, int R, int lane, const float* v) {
    int rb = R >> 4, ri = R & 15;
    int ks = lane >> 2;
    int lA = 4 * (ri & 7) + 2 * (lane & 1);
    int s  = 2 * ((lane >> 1) & 1) + (ri >= 8 ? 1 : 0);
    char* base = plane + (size_t)rb * 4096 + ks * 512 + s * 4;
    unsigned h01, h23, l01, l23;
    split4(v, h01, h23, l01, l23);
    *(unsigned*)(base + lA * 16)            = h01;
    *(unsigned*)(base + (lA + 1) * 16)      = h23;
    *(unsigned*)(base + PLANE_BYTES + lA * 16)       = l01;
    *(unsigned*)(base + PLANE_BYTES + (lA + 1) * 16) = l23;
}
// row-warp split load (reconstruct f32 = hi + lo)
__device__ __forceinline__ void split_load_row(const char* plane, int R, int lane, float* v) {
    int rb = R >> 4, ri = R & 15;
    int ks = lane >> 2;
    int lA = 4 * (ri & 7) + 2 * (lane & 1);
    int s  = 2 * ((lane >> 1) & 1) + (ri >= 8 ? 1 : 0);
    const char* base = plane + (size_t)rb * 4096 + ks * 512 + s * 4;
    unsigned h01 = *(const unsigned*)(base + lA * 16);
    unsigned h23 = *(const unsigned*)(base + (lA + 1) * 16);
    unsigned l01 = *(const unsigned*)(base + PLANE_BYTES + lA * 16);
    unsigned l23 = *(const unsigned*)(base + PLANE_BYTES + (lA + 1) * 16);
    float2 fh0 = __bfloat1622float2(*(__nv_bfloat162*)&h01);
    float2 fh1 = __bfloat1622float2(*(__nv_bfloat162*)&h23);
    float2 fl0 = __bfloat1622float2(*(__nv_bfloat162*)&l01);
    float2 fl1 = __bfloat1622float2(*(__nv_bfloat162*)&l23);
    v[0] = fh0.x + fl0.x; v[1] = fh0.y + fl0.y;
    v[2] = fh1.x + fl1.x; v[3] = fh1.y + fl1.y;
}

// ======================= CSR build =======================
__global__ void k_zero_rowptr() {
    int i = blockIdx.x * blockDim.x + threadIdx.x;
    if (i < NP1) g_rowptr[i] = 0;
}
__global__ void k_hist(const int* __restrict__ rows) {
    int e = blockIdx.x * blockDim.x + threadIdx.x;
    if (e < N_EDGES) atomicAdd(&g_rowptr[rows[e] + 1], 1);
}
__global__ void k_scan1() {
    __shared__ int s[1024];
    int t = threadIdx.x, i = blockIdx.x * 1024 + t;
    int v = (i < NP1) ? g_rowptr[i] : 0;
    s[t] = v; __syncthreads();
    #pragma unroll
    for (int off = 1; off < 1024; off <<= 1) {
        int tv = 0;
        if (t >= off) tv = s[t - off];
        __syncthreads(); s[t] += tv; __syncthreads();
    }
    if (i < NP1) g_rowptr[i] = s[t];
    if (t == 1023) g_bsum[blockIdx.x] = s[1023];
}
__global__ void k_scan2() {
    int acc = 0;
    for (int b = 0; b < NSCAN_BLOCKS; b++) { acc += g_bsum[b]; g_bsum[b] = acc; }
}
__global__ void k_scan3() {
    int b = blockIdx.x;
    int i = b * 1024 + threadIdx.x;
    int add = b ? g_bsum[b - 1] : 0;
    if (i < NP1) {
        int v = g_rowptr[i] + add;
        g_rowptr[i] = v;
        if (i < N_NODES) g_pos[i] = v;
    }
}
__global__ void k_fill(const int* __restrict__ rows, const int* __restrict__ cols,
                       const float* __restrict__ vals) {
    int e = blockIdx.x * blockDim.x + threadIdx.x;
    if (e >= N_EDGES) return;
    int r = rows[e];
    int p = atomicAdd(&g_pos[r], 1);
    g_ecol[p] = cols[e];
    g_eval[p] = vals[e];
}

// ======================= weight prep: pack B in mma-fragment order ==============
__global__ void k_wprep(const float* __restrict__ fc1w, const float* __restrict__ fc2w,
                        const float* __restrict__ w0n, const float* __restrict__ w0s,
                        const float* __restrict__ w1n, const float* __restrict__ w1s,
                        const float* __restrict__ w2n, const float* __restrict__ w2s,
                        const float* __restrict__ w3n, const float* __restrict__ w3s,
                        __nv_bfloat16* __restrict__ wt)
{
    int t = blockIdx.y, n = blockIdx.x, k = threadIdx.x;
    float v;
    switch (t) {
        case 0: v = fc1w[n * 128 + k]; break;
        case 1: v = fc2w[n * 128 + k]; break;
        case 2: v = w0n[k * 128 + n]; break;
        case 3: v = w0s[k * 128 + n]; break;
        case 4: v = w1n[k * 128 + n]; break;
        case 5: v = w1s[k * 128 + n]; break;
        case 6: v = w2n[k * 128 + n]; break;
        case 7: v = w2s[k * 128 + n]; break;
        default: v = (n < 64) ? w3n[k * 64 + n] : w3s[k * 64 + (n - 64)]; break;
    }
    __nv_bfloat16 hi = __float2bfloat16_rn(v);
    __nv_bfloat16 lo = __float2bfloat16_rn(v - __bfloat162float(hi));

    int ks = k >> 4, kk = k & 15;
    int q, e;
    if (kk < 8) { q = kk >> 1; e = kk & 1; }
    else        { q = (kk - 8) >> 1; e = 2 + (kk & 1); }
    int nb = n >> 3, n7 = n & 7;
    char* base = (char*)wt + (size_t)t * WT_TILE_BYTES
               + ((nb * 8 + ks) * 512) + n7 * 64 + q * 16;
    *(__nv_bfloat16*)(base + e * 2)     = hi;
    *(__nv_bfloat16*)(base + 8 + e * 2) = lo;
}

// ======================= X prep: f32 row-major -> split fragment layout =========
__global__ __launch_bounds__(256) void k_xprep(const float* __restrict__ X, char* __restrict__ dst) {
    int R = blockIdx.x * 8 + (threadIdx.x >> 5);
    int lane = threadIdx.x & 31;
    float v[4] = {0.f, 0.f, 0.f, 0.f};
    if (R < N_NODES) {
        float4 f = *(const float4*)&X[(size_t)R * 128 + lane * 4];
        v[0] = f.x; v[1] = f.y; v[2] = f.z; v[3] = f.w;
    }
    split_store_row(dst, R, lane, v);
}

// ======================= fragment-direct bf16 GEMM (no smem, no syncs) ==========
// A: split fragment buffer (hi plane + lo at +PLANE). B: packed tiles.
// modes: 0 = bias+relu -> split-write o0 ; 1 = fp16 supn (ld128) ;
//        2 = f32 self (ld128) ; 3 = split64: wn<2 -> fp16 o0, wn>=2 -> f32 o1
__global__ __launch_bounds__(256, 2) void k_mm(
    const char* __restrict__ Asp,
    const __nv_bfloat16* __restrict__ Bw,
    const float* __restrict__ bias,
    void* __restrict__ o0, int m0,
    void* __restrict__ o1, int m1,
    int nH)
{
    const int tid = threadIdx.x, wid = tid >> 5, lane = tid & 31;
    const int wm = wid >> 2, wn = wid & 3;   // warp tile: 64 rows x 32 cols
    const int row0 = blockIdx.x * 128;

    // per-lane A base: 16B fragment per (rb, ks)
    const char* aB = Asp + (size_t)((row0 >> 4) + wm * 4) * 4096 + lane * 16;
    const char* bLane = (const char*)Bw + (lane >> 2) * 64 + (lane & 3) * 16;

    for (int nh = 0; nh < nH; nh++) {
        const char* Bt = bLane + (size_t)nh * WT_TILE_BYTES;

        float acc[4][4][4];
        #pragma unroll
        for (int i = 0; i < 4; i++)
            #pragma unroll
            for (int j = 0; j < 4; j++)
                #pragma unroll
                for (int q = 0; q < 4; q++) acc[i][j][q] = 0.f;

        #pragma unroll
        for (int ks = 0; ks < 8; ks++) {
            uint4 bv[4], ah[4], al[4];
            #pragma unroll
            for (int j = 0; j < 4; j++)
                bv[j] = *(const uint4*)(Bt + ((wn * 4 + j) * 8 + ks) * 512);
            #pragma unroll
            for (int i = 0; i < 4; i++)
                ah[i] = *(const uint4*)(aB + i * 4096 + ks * 512);
            #pragma unroll
            for (int i = 0; i < 4; i++)
                al[i] = *(const uint4*)(aB + PLANE_BYTES + i * 4096 + ks * 512);

            #pragma unroll
            for (int i = 0; i < 4; i++)
                #pragma unroll
                for (int j = 0; j < 4; j++)
                    mma_bf16(acc[i][j], (const unsigned*)&ah[i], bv[j].x, bv[j].y);
            #pragma unroll
            for (int i = 0; i < 4; i++)
                #pragma unroll
                for (int j = 0; j < 4; j++)
                    mma_bf16(acc[i][j], (const unsigned*)&ah[i], bv[j].z, bv[j].w);
            #pragma unroll
            for (int i = 0; i < 4; i++)
                #pragma unroll
                for (int j = 0; j < 4; j++)
                    mma_bf16(acc[i][j], (const unsigned*)&al[i], bv[j].x, bv[j].y);
        }

        const int mode = (nh == 0) ? m0 : m1;
        const int cb = wn * 32 + 2 * (lane & 3);
        const int rb = row0 + wm * 64 + (lane >> 2);

        if (mode == 0) {
            // bias + relu + split-fragment write
            float2 bvv[4];
            #pragma unroll
            for (int j = 0; j < 4; j++) bvv[j] = *(const float2*)&bias[cb + j * 8];
            char* outp = (char*)o0;
            const int lA = 4 * (lane >> 2) + (lane & 3);
            #pragma unroll
            for (int i = 0; i < 4; i++) {
                size_t rbb = (size_t)((row0 >> 4) + wm * 4 + i) * 4096;
                #pragma unroll
                for (int j = 0; j < 4; j++) {
                    float v[4];
                    v[0] = fmaxf(acc[i][j][0] + bvv[j].x, 0.f);
                    v[1] = fmaxf(acc[i][j][1] + bvv[j].y, 0.f);
                    v[2] = fmaxf(acc[i][j][2] + bvv[j].x, 0.f);
                    v[3] = fmaxf(acc[i][j][3] + bvv[j].y, 0.f);
                    unsigned h01, h23, l01, l23;
                    split4(v, h01, h23, l01, l23);
                    char* p = outp + rbb + (2 * wn + (j >> 1)) * 512 + lA * 16 + (j & 1) * 8;
                    *(uint2*)p = make_uint2(h01, h23);
                    *(uint2*)(p + PLANE_BYTES) = make_uint2(l01, l23);
                }
            }
        } else if (mode == 1) {
            __half* out = (__half*)o0;
            #pragma unroll
            for (int i = 0; i < 4; i++) {
                size_t r1 = (size_t)(rb + i * 16) * 128;
                size_t r2 = r1 + 8 * 128;
                #pragma unroll
                for (int j = 0; j < 4; j++) {
                    float* a = acc[i][j];
                    int c = cb + j * 8;
                    *(__half2*)&out[r1 + c] = __floats2half2_rn(a[0], a[1]);
                    *(__half2*)&out[r2 + c] = __floats2half2_rn(a[2], a[3]);
                }
            }
        } else if (mode == 2) {
            float* out = (float*)o1;
            #pragma unroll
            for (int i = 0; i < 4; i++) {
                size_t r1 = (size_t)(rb + i * 16) * 128;
                size_t r2 = r1 + 8 * 128;
                #pragma unroll
                for (int j = 0; j < 4; j++) {
                    float* a = acc[i][j];
                    int c = cb + j * 8;
                    *(float2*)&out[r1 + c] = make_float2(a[0], a[1]);
                    *(float2*)&out[r2 + c] = make_float2(a[2], a[3]);
                }
            }
        } else {   // mode 3
            if (wn < 2) {
                __half* out = (__half*)o0;
                #pragma unroll
                for (int i = 0; i < 4; i++) {
                    size_t r1 = (size_t)(rb + i * 16) * 64;
                    size_t r2 = r1 + 8 * 64;
                    #pragma unroll
                    for (int j = 0; j < 4; j++) {
                        float* a = acc[i][j];
                        int c = cb + j * 8;
                        *(__half2*)&out[r1 + c] = __floats2half2_rn(a[0], a[1]);
                        *(__half2*)&out[r2 + c] = __floats2half2_rn(a[2], a[3]);
                    }
                }
            } else {
                float* out = (float*)o1;
                #pragma unroll
                for (int i = 0; i < 4; i++) {
                    size_t r1 = (size_t)(rb + i * 16) * 64;
                    size_t r2 = r1 + 8 * 64;
                    #pragma unroll
                    for (int j = 0; j < 4; j++) {
                        float* a = acc[i][j];
                        int c = cb + j * 8 - 64;
                        *(float2*)&out[r1 + c] = make_float2(a[0], a[1]);
                        *(float2*)&out[r2 + c] = make_float2(a[2], a[3]);
                    }
                }
            }
        }
    }
}

// ======================= LayerNorm (split in -> split out) =======================
__global__ __launch_bounds__(256) void k_ln(const char* __restrict__ in,
                                            char* __restrict__ out,
                                            const float* __restrict__ g,
                                            const float* __restrict__ b)
{
    int R    = blockIdx.x * 8 + (threadIdx.x >> 5);
    int lane = threadIdx.x & 31;
    float v[4];
    split_load_row(in, R, lane, v);
    float s = v[0] + v[1] + v[2] + v[3];
    #pragma unroll
    for (int o = 16; o; o >>= 1) s += __shfl_xor_sync(0xffffffffu, s, o);
    float mean = s * (1.f / 128.f);
    float d0 = v[0] - mean, d1 = v[1] - mean, d2 = v[2] - mean, d3 = v[3] - mean;
    float ss = d0 * d0 + d1 * d1 + d2 * d2 + d3 * d3;
    #pragma unroll
    for (int o = 16; o; o >>= 1) ss += __shfl_xor_sync(0xffffffffu, ss, o);
    float inv = 1.f / (sqrtf(ss * (1.f / 127.f)) + 1e-6f);
    float4 gg = *(const float4*)&g[lane * 4];
    float4 bb = *(const float4*)&b[lane * 4];
    float o4[4];
    o4[0] = gg.x * d0 * inv + bb.x;
    o4[1] = gg.y * d1 * inv + bb.y;
    o4[2] = gg.z * d2 * inv + bb.z;
    o4[3] = gg.w * d3 * inv + bb.w;
    split_store_row(out, R, lane, o4);
}

// ======================= GCN aggregate (fp16 gather) =======================
// SPLIT=1: relu -> split-fragment write (OUT=128). SPLIT=0: relu -> f32 row-major.
template <int OUT, int SPLIT>
__global__ __launch_bounds__(256) void k_agg(const __half* __restrict__ supn,
                                             const float* __restrict__ selfm,
                                             const float* __restrict__ bias,
                                             void* __restrict__ out)
{
    const int V = OUT / 32;
    int node = blockIdx.x * 8 + (threadIdx.x >> 5);
    int lane = threadIdx.x & 31;

    float acc[V];
    {
        const float* sr = selfm + (size_t)node * OUT + lane * V;
        #pragma unroll
        for (int i = 0; i < V; i++) acc[i] = sr[i] + bias[lane * V + i];
    }

    int e0 = g_rowptr[node], e1 = g_rowptr[node + 1];
    for (int eb = e0; eb < e1; eb += 32) {
        int rem = e1 - eb;
        int c = 0; float wv = 0.f;
        if (lane < rem) { c = g_ecol[eb + lane]; wv = g_eval[eb + lane]; }
        if (rem >= 32) {
            #pragma unroll 8
            for (int j = 0; j < 32; j++) {
                int   cj = __shfl_sync(0xffffffffu, c, j);
                float wj = __shfl_sync(0xffffffffu, wv, j);
                const __half* srow = supn + (size_t)cj * OUT + lane * V;
                if (V == 4) {
                    uint2 u = *(const uint2*)srow;
                    float2 f0 = __half22float2(*(const __half2*)&u.x);
                    float2 f1 = __half22float2(*(const __half2*)&u.y);
                    acc[0] = fmaf(wj, f0.x, acc[0]);
                    acc[1] = fmaf(wj, f0.y, acc[1]);
                    acc[2] = fmaf(wj, f1.x, acc[2]);
                    acc[3] = fmaf(wj, f1.y, acc[3]);
                } else {
                    uint32_t u = *(const uint32_t*)srow;
                    float2 f0 = __half22float2(*(const __half2*)&u);
                    acc[0] = fmaf(wj, f0.x, acc[0]);
                    acc[1] = fmaf(wj, f0.y, acc[1]);
                }
            }
        } else {
            for (int j = 0; j < rem; j++) {
                int   cj = __shfl_sync(0xffffffffu, c, j);
                float wj = __shfl_sync(0xffffffffu, wv, j);
                const __half* srow = supn + (size_t)cj * OUT + lane * V;
                if (V == 4) {
                    uint2 u = *(const uint2*)srow;
                    float2 f0 = __half22float2(*(const __half2*)&u.x);
                    float2 f1 = __half22float2(*(const __half2*)&u.y);
                    acc[0] = fmaf(wj, f0.x, acc[0]);
                    acc[1] = fmaf(wj, f0.y, acc[1]);
                    acc[2] = fmaf(wj, f1.x, acc[2]);
                    acc[3] = fmaf(wj, f1.y, acc[3]);
                } else {
                    uint32_t u = *(const uint32_t*)srow;
                    float2 f0 = __half22float2(*(const __half2*)&u);
                    acc[0] = fmaf(wj, f0.x, acc[0]);
                    acc[1] = fmaf(wj, f0.y, acc[1]);
                }
            }
        }
    }

    if (SPLIT) {
        float v[4];
        #pragma unroll
        for (int i = 0; i < 4; i++) v[i] = fmaxf(acc[i], 0.f);
        split_store_row((char*)out, node, lane, v);
    } else {
        float* orow = (float*)out + (size_t)node * OUT + lane * V;
        #pragma unroll
        for (int i = 0; i < V; i++) orow[i] = fmaxf(acc[i], 0.f);
    }
}

// ======================= launch =======================
extern "C" void kernel_launch(void* const* d_in, const int* in_sizes, int n_in,
                              void* d_out, int out_size)
{
    const float* x    = (const float*)d_in[0];
    const int*   er   = (const int*)d_in[1];
    const int*   ec   = (const int*)d_in[2];
    const float* ev   = (const float*)d_in[3];
    const float* fc1w = (const float*)d_in[4];
    const float* fc1b = (const float*)d_in[5];
    const float* fc2w = (const float*)d_in[6];
    const float* fc2b = (const float*)d_in[7];
    const float* lng  = (const float*)d_in[8];
    const float* lnb  = (const float*)d_in[9];
    const float *wn[4], *wsf[4], *gb[4];
    for (int i = 0; i < 4; i++) {
        wn[i]  = (const float*)d_in[10 + 3 * i];
        wsf[i] = (const float*)d_in[11 + 3 * i];
        gb[i]  = (const float*)d_in[12 + 3 * i];
    }
    float* outp = (float*)d_out;

    char *s0, *s1;
    float* selfb;
    __half* supn;
    __nv_bfloat16* wt;
    cudaGetSymbolAddress((void**)&s0,    g_h0);
    cudaGetSymbolAddress((void**)&s1,    g_h1);
    cudaGetSymbolAddress((void**)&supn,  g_supn);
    cudaGetSymbolAddress((void**)&selfb, g_self);
    cudaGetSymbolAddress((void**)&wt,    g_wt);
    auto WT = [&](int t) { return wt + (size_t)t * 32768; };

    const int MT = (N_NODES + 127) / 128;   // 782

    k_wprep<<<dim3(128, 9), 128>>>(fc1w, fc2w, wn[0], wsf[0], wn[1], wsf[1],
                                   wn[2], wsf[2], wn[3], wsf[3], wt);            // 0
    k_xprep<<<NPAD / 8, 256>>>(x, s0);                                           // 1
    k_zero_rowptr<<<(NP1 + 255) / 256, 256>>>();                                 // 2
    k_mm<<<MT, 256>>>(s0, WT(0), fc1b, s1, 0, nullptr, 0, 1);                    // 3 <- profiled
    k_hist<<<(N_EDGES + 255) / 256, 256>>>(er);                                  // 4
    k_scan1<<<NSCAN_BLOCKS, 1024>>>();                                           // 5
    k_scan2<<<1, 1>>>();                                                         // 6
    k_scan3<<<NSCAN_BLOCKS, 1024>>>();                                           // 7
    k_fill<<<(N_EDGES + 255) / 256, 256>>>(er, ec, ev);                          // 8
    k_mm<<<MT, 256>>>(s1, WT(1), fc2b, s0, 0, nullptr, 0, 1);                    // 9
    k_ln<<<N_NODES / 8, 256>>>(s0, s1, lng, lnb);                                // 10

    char* cur = s1;
    char* nxt = s0;
    for (int l = 0; l < 3; l++) {
        k_mm<<<MT, 256>>>(cur, WT(2 + 2 * l), nullptr, supn, 1, selfb, 2, 2);
        k_agg<128, 1><<<N_NODES / 8, 256>>>(supn, selfb, gb[l], nxt);
        char* t = cur; cur = nxt; nxt = t;
    }

    k_mm<<<MT, 256>>>(cur, WT(8), nullptr, supn, 3, selfb, 3, 1);
    k_agg<64, 0><<<N_NODES / 8, 256>>>(supn, selfb, gb[3], outp);
}

// round 9
// speedup vs baseline: 1.8859x; 1.8859x over previous
#include <cuda_runtime.h>
#include <cuda_bf16.h>
#include <cuda_fp16.h>
#include <math.h>
#include <stdint.h>

#define N_NODES 100000
#define NPAD    100096
#define N_EDGES 3200000
#define NP1     100001
#define NSCAN_BLOCKS 98

#define LDAB 264                       // A smem row stride (bf16): [hi 128 | lo 128 | pad]
#define A_BYTES (128 * LDAB * 2)       // 67584
#define WT_TILE_BYTES 65536            // packed B tile: 16 nb x 8 ks x 512B

// ======================= device scratch =======================
__device__ int    g_rowptr[NP1];
__device__ int    g_bsum[128];
__device__ int    g_pos[N_NODES];
__device__ int    g_ecol[N_EDGES];
__device__ float  g_eval[N_EDGES];
__device__ float  g_h0[(size_t)NPAD * 128];   // split act buffer A (512B/row: hi|lo)
__device__ float  g_h1[(size_t)NPAD * 128];   // split act buffer B
__device__ __half g_supn[(size_t)NPAD * 128];
__device__ float  g_self[(size_t)NPAD * 128];
__device__ __nv_bfloat16 g_wt[9 * 32768];

// ======================= helpers =======================
__device__ __forceinline__ uint32_t smem_u32(const void* p) {
    uint32_t a;
    asm("{ .reg .u64 t; cvta.to.shared.u64 t, %1; cvt.u32.u64 %0, t; }" : "=r"(a) : "l"(p));
    return a;
}
__device__ __forceinline__ void ldsm_x4(unsigned* r, uint32_t addr) {
    asm volatile("ldmatrix.sync.aligned.m8n8.x4.shared.b16 {%0,%1,%2,%3}, [%4];"
        : "=r"(r[0]), "=r"(r[1]), "=r"(r[2]), "=r"(r[3]) : "r"(addr));
}
__device__ __forceinline__ void mma_bf16(float* c, const unsigned* a, unsigned b0, unsigned b1) {
    asm volatile("mma.sync.aligned.m16n8k16.row.col.f32.bf16.bf16.f32 "
        "{%0,%1,%2,%3}, {%4,%5,%6,%7}, {%8,%9}, {%0,%1,%2,%3};"
        : "+f"(c[0]), "+f"(c[1]), "+f"(c[2]), "+f"(c[3])
        : "r"(a[0]), "r"(a[1]), "r"(a[2]), "r"(a[3]), "r"(b0), "r"(b1));
}
__device__ __forceinline__ void cpasync16(uint32_t dst, const void* src) {
    asm volatile("cp.async.cg.shared.global [%0], [%1], 16;" :: "r"(dst), "l"(src));
}
__device__ __forceinline__ unsigned pk(float a, float b) {
    __nv_bfloat162 h = __floats2bfloat162_rn(a, b);
    return *(unsigned*)&h;
}
// split pair (a0,a1) -> hi bf16x2 + lo bf16x2
__device__ __forceinline__ void split2(float a0, float a1, unsigned& hi, unsigned& lo) {
    __nv_bfloat16 h0 = __float2bfloat16_rn(a0);
    __nv_bfloat16 h1 = __float2bfloat16_rn(a1);
    hi = pk(__bfloat162float(h0), __bfloat162float(h1));
    lo = pk(a0 - __bfloat162float(h0), a1 - __bfloat162float(h1));
}
// row-major split store: lane owns cols 4L..4L+3 of row R (buf row = 512B: hi|lo)
__device__ __forceinline__ void split_store_rm(char* buf, int R, int lane, const float* v) {
    unsigned h01, h23, l01, l23;
    split2(v[0], v[1], h01, l01);
    split2(v[2], v[3], h23, l23);
    char* p = buf + (size_t)R * 512 + lane * 8;
    *(uint2*)p = make_uint2(h01, h23);
    *(uint2*)(p + 256) = make_uint2(l01, l23);
}
__device__ __forceinline__ void split_load_rm(const char* buf, int R, int lane, float* v) {
    const char* p = buf + (size_t)R * 512 + lane * 8;
    uint2 h = *(const uint2*)p;
    uint2 l = *(const uint2*)(p + 256);
    float2 fh0 = __bfloat1622float2(*(__nv_bfloat162*)&h.x);
    float2 fh1 = __bfloat1622float2(*(__nv_bfloat162*)&h.y);
    float2 fl0 = __bfloat1622float2(*(__nv_bfloat162*)&l.x);
    float2 fl1 = __bfloat1622float2(*(__nv_bfloat162*)&l.y);
    v[0] = fh0.x + fl0.x; v[1] = fh0.y + fl0.y;
    v[2] = fh1.x + fl1.x; v[3] = fh1.y + fl1.y;
}

// ======================= CSR build =======================
__global__ void k_zero_rowptr() {
    int i = blockIdx.x * blockDim.x + threadIdx.x;
    if (i < NP1) g_rowptr[i] = 0;
}
__global__ void k_hist(const int* __restrict__ rows) {
    int e = blockIdx.x * blockDim.x + threadIdx.x;
    if (e < N_EDGES) atomicAdd(&g_rowptr[rows[e] + 1], 1);
}
__global__ void k_scan1() {
    __shared__ int s[1024];
    int t = threadIdx.x, i = blockIdx.x * 1024 + t;
    int v = (i < NP1) ? g_rowptr[i] : 0;
    s[t] = v; __syncthreads();
    #pragma unroll
    for (int off = 1; off < 1024; off <<= 1) {
        int tv = 0;
        if (t >= off) tv = s[t - off];
        __syncthreads(); s[t] += tv; __syncthreads();
    }
    if (i < NP1) g_rowptr[i] = s[t];
    if (t == 1023) g_bsum[blockIdx.x] = s[1023];
}
__global__ void k_scan2() {
    int acc = 0;
    for (int b = 0; b < NSCAN_BLOCKS; b++) { acc += g_bsum[b]; g_bsum[b] = acc; }
}
__global__ void k_scan3() {
    int b = blockIdx.x;
    int i = b * 1024 + threadIdx.x;
    int add = b ? g_bsum[b - 1] : 0;
    if (i < NP1) {
        int v = g_rowptr[i] + add;
        g_rowptr[i] = v;
        if (i < N_NODES) g_pos[i] = v;
    }
}
__global__ void k_fill(const int* __restrict__ rows, const int* __restrict__ cols,
                       const float* __restrict__ vals) {
    int e = blockIdx.x * blockDim.x + threadIdx.x;
    if (e >= N_EDGES) return;
    int r = rows[e];
    int p = atomicAdd(&g_pos[r], 1);
    g_ecol[p] = cols[e];
    g_eval[p] = vals[e];
}

// ======================= weight prep: pack B in mma-fragment order ==============
__global__ void k_wprep(const float* __restrict__ fc1w, const float* __restrict__ fc2w,
                        const float* __restrict__ w0n, const float* __restrict__ w0s,
                        const float* __restrict__ w1n, const float* __restrict__ w1s,
                        const float* __restrict__ w2n, const float* __restrict__ w2s,
                        const float* __restrict__ w3n, const float* __restrict__ w3s,
                        __nv_bfloat16* __restrict__ wt)
{
    int t = blockIdx.y, n = blockIdx.x, k = threadIdx.x;
    float v;
    switch (t) {
        case 0: v = fc1w[n * 128 + k]; break;
        case 1: v = fc2w[n * 128 + k]; break;
        case 2: v = w0n[k * 128 + n]; break;
        case 3: v = w0s[k * 128 + n]; break;
        case 4: v = w1n[k * 128 + n]; break;
        case 5: v = w1s[k * 128 + n]; break;
        case 6: v = w2n[k * 128 + n]; break;
        case 7: v = w2s[k * 128 + n]; break;
        default: v = (n < 64) ? w3n[k * 64 + n] : w3s[k * 64 + (n - 64)]; break;
    }
    __nv_bfloat16 hi = __float2bfloat16_rn(v);
    __nv_bfloat16 lo = __float2bfloat16_rn(v - __bfloat162float(hi));

    int ks = k >> 4, kk = k & 15;
    int q, e;
    if (kk < 8) { q = kk >> 1; e = kk & 1; }
    else        { q = (kk - 8) >> 1; e = 2 + (kk & 1); }
    int nb = n >> 3, n7 = n & 7;
    char* base = (char*)wt + (size_t)t * WT_TILE_BYTES
               + ((nb * 8 + ks) * 512) + n7 * 64 + q * 16;
    *(__nv_bfloat16*)(base + e * 2)     = hi;
    *(__nv_bfloat16*)(base + 8 + e * 2) = lo;
}

// ======================= X prep: f32 -> split rows =======================
__global__ __launch_bounds__(256) void k_xprep(const float* __restrict__ X, char* __restrict__ dst) {
    int R = blockIdx.x * 8 + (threadIdx.x >> 5);
    int lane = threadIdx.x & 31;
    float v[4] = {0.f, 0.f, 0.f, 0.f};
    if (R < N_NODES) {
        float4 f = *(const float4*)&X[(size_t)R * 128 + lane * 4];
        v[0] = f.x; v[1] = f.y; v[2] = f.z; v[3] = f.w;
    }
    split_store_rm(dst, R, lane, v);
}

// ======================= bf16 GEMM: cp.async split-A -> smem, ldsm, HMMA ========
// modes: 0 = bias+relu -> split rows o0 ; 1 = fp16 supn (ld128) ;
//        2 = f32 self (ld128) ; 3 = split64: wn<2 -> fp16 o0 (ld64), wn>=2 -> f32 o1 (ld64)
__global__ __launch_bounds__(256, 2) void k_mm(
    const char* __restrict__ Asp,
    const __nv_bfloat16* __restrict__ Bw,
    const float* __restrict__ bias,
    void* __restrict__ o0, int m0,
    void* __restrict__ o1, int m1,
    int nH)
{
    extern __shared__ __nv_bfloat16 As[];   // 128 x LDAB

    const int tid = threadIdx.x, wid = tid >> 5, lane = tid & 31;
    const int wm = wid >> 2, wn = wid & 3;   // warp tile: 64 rows x 32 cols
    const int row0 = blockIdx.x * 128;

    // ---- prologue: pure async copy of pre-split A tile (64KB) ----
    {
        const uint32_t sbase = smem_u32(As);
        const char* gsrc = Asp + (size_t)row0 * 512;
        #pragma unroll
        for (int it = 0; it < 16; it++) {
            int i = tid + 256 * it;          // 4096 x 16B
            int r = i >> 5, c = i & 31;
            cpasync16(sbase + r * (LDAB * 2) + c * 16, gsrc + (size_t)i * 16);
        }
        asm volatile("cp.async.commit_group;" ::: "memory");
        asm volatile("cp.async.wait_group 0;" ::: "memory");
    }
    __syncthreads();

    const uint32_t aBase = smem_u32(As) +
        2u * (uint32_t)((wm * 64 + (lane & 15)) * LDAB + ((lane >> 4) << 3));
    const char* bLane = (const char*)Bw + (lane >> 2) * 64 + (lane & 3) * 16;

    for (int nh = 0; nh < nH; nh++) {
        const char* Bt = bLane + (size_t)nh * WT_TILE_BYTES;

        float acc[4][4][4];
        #pragma unroll
        for (int i = 0; i < 4; i++)
            #pragma unroll
            for (int j = 0; j < 4; j++)
                #pragma unroll
                for (int q = 0; q < 4; q++) acc[i][j][q] = 0.f;

        #pragma unroll
        for (int ks = 0; ks < 8; ks++) {
            const int ka = ks * 16;
            uint4 bv[4];
            #pragma unroll
            for (int j = 0; j < 4; j++)
                bv[j] = *(const uint4*)(Bt + ((wn * 4 + j) * 8 + ks) * 512);

            unsigned ah[4][4];
            #pragma unroll
            for (int i = 0; i < 4; i++)
                ldsm_x4(ah[i], aBase + 2u * (uint32_t)(i * 16 * LDAB + ka));
            #pragma unroll
            for (int i = 0; i < 4; i++)
                #pragma unroll
                for (int j = 0; j < 4; j++)
                    mma_bf16(acc[i][j], ah[i], bv[j].x, bv[j].y);   // Ah Bh
            {
                unsigned al[4][4];
                #pragma unroll
                for (int i = 0; i < 4; i++)
                    ldsm_x4(al[i], aBase + 2u * (uint32_t)(i * 16 * LDAB + ka + 128));
                #pragma unroll
                for (int i = 0; i < 4; i++)
                    #pragma unroll
                    for (int j = 0; j < 4; j++)
                        mma_bf16(acc[i][j], al[i], bv[j].x, bv[j].y);   // Al Bh
            }
            #pragma unroll
            for (int i = 0; i < 4; i++)
                #pragma unroll
                for (int j = 0; j < 4; j++)
                    mma_bf16(acc[i][j], ah[i], bv[j].z, bv[j].w);   // Ah Bl
        }

        // ---- register epilogue (NPAD-padded outputs: no row guard) ----
        const int mode = (nh == 0) ? m0 : m1;
        const int cb = wn * 32 + 2 * (lane & 3);
        const int rb = row0 + wm * 64 + (lane >> 2);

        if (mode == 0) {
            // bias + relu -> split rows
            float2 bvv[4];
            #pragma unroll
            for (int j = 0; j < 4; j++) bvv[j] = *(const float2*)&bias[cb + j * 8];
            char* outp = (char*)o0;
            #pragma unroll
            for (int i = 0; i < 4; i++) {
                char* p1 = outp + (size_t)(rb + i * 16) * 512;
                char* p2 = p1 + 8 * 512;
                #pragma unroll
                for (int j = 0; j < 4; j++) {
                    float* a = acc[i][j];
                    int c2 = (cb + j * 8) * 2;
                    unsigned hi, lo;
                    split2(fmaxf(a[0] + bvv[j].x, 0.f), fmaxf(a[1] + bvv[j].y, 0.f), hi, lo);
                    *(unsigned*)(p1 + c2) = hi;
                    *(unsigned*)(p1 + 256 + c2) = lo;
                    split2(fmaxf(a[2] + bvv[j].x, 0.f), fmaxf(a[3] + bvv[j].y, 0.f), hi, lo);
                    *(unsigned*)(p2 + c2) = hi;
                    *(unsigned*)(p2 + 256 + c2) = lo;
                }
            }
        } else if (mode == 1) {
            __half* out = (__half*)o0;
            #pragma unroll
            for (int i = 0; i < 4; i++) {
                size_t r1 = (size_t)(rb + i * 16) * 128;
                size_t r2 = r1 + 8 * 128;
                #pragma unroll
                for (int j = 0; j < 4; j++) {
                    float* a = acc[i][j];
                    int c = cb + j * 8;
                    *(__half2*)&out[r1 + c] = __floats2half2_rn(a[0], a[1]);
                    *(__half2*)&out[r2 + c] = __floats2half2_rn(a[2], a[3]);
                }
            }
        } else if (mode == 2) {
            float* out = (float*)o1;
            #pragma unroll
            for (int i = 0; i < 4; i++) {
                size_t r1 = (size_t)(rb + i * 16) * 128;
                size_t r2 = r1 + 8 * 128;
                #pragma unroll
                for (int j = 0; j < 4; j++) {
                    float* a = acc[i][j];
                    int c = cb + j * 8;
                    *(float2*)&out[r1 + c] = make_float2(a[0], a[1]);
                    *(float2*)&out[r2 + c] = make_float2(a[2], a[3]);
                }
            }
        } else {   // mode 3
            if (wn < 2) {
                __half* out = (__half*)o0;
                #pragma unroll
                for (int i = 0; i < 4; i++) {
                    size_t r1 = (size_t)(rb + i * 16) * 64;
                    size_t r2 = r1 + 8 * 64;
                    #pragma unroll
                    for (int j = 0; j < 4; j++) {
                        float* a = acc[i][j];
                        int c = cb + j * 8;
                        *(__half2*)&out[r1 + c] = __floats2half2_rn(a[0], a[1]);
                        *(__half2*)&out[r2 + c] = __floats2half2_rn(a[2], a[3]);
                    }
                }
            } else {
                float* out = (float*)o1;
                #pragma unroll
                for (int i = 0; i < 4; i++) {
                    size_t r1 = (size_t)(rb + i * 16) * 64;
                    size_t r2 = r1 + 8 * 64;
                    #pragma unroll
                    for (int j = 0; j < 4; j++) {
                        float* a = acc[i][j];
                        int c = cb + j * 8 - 64;
                        *(float2*)&out[r1 + c] = make_float2(a[0], a[1]);
                        *(float2*)&out[r2 + c] = make_float2(a[2], a[3]);
                    }
                }
            }
        }
    }
}

// ======================= LayerNorm (split in -> split out) =======================
__global__ __launch_bounds__(256) void k_ln(const char* __restrict__ in,
                                            char* __restrict__ out,
                                            const float* __restrict__ g,
                                            const float* __restrict__ b)
{
    int R    = blockIdx.x * 8 + (threadIdx.x >> 5);
    int lane = threadIdx.x & 31;
    float v[4];
    split_load_rm(in, R, lane, v);
    float s = v[0] + v[1] + v[2] + v[3];
    #pragma unroll
    for (int o = 16; o; o >>= 1) s += __shfl_xor_sync(0xffffffffu, s, o);
    float mean = s * (1.f / 128.f);
    float d0 = v[0] - mean, d1 = v[1] - mean, d2 = v[2] - mean, d3 = v[3] - mean;
    float ss = d0 * d0 + d1 * d1 + d2 * d2 + d3 * d3;
    #pragma unroll
    for (int o = 16; o; o >>= 1) ss += __shfl_xor_sync(0xffffffffu, ss, o);
    float inv = 1.f / (sqrtf(ss * (1.f / 127.f)) + 1e-6f);
    float4 gg = *(const float4*)&g[lane * 4];
    float4 bb = *(const float4*)&b[lane * 4];
    float o4[4];
    o4[0] = gg.x * d0 * inv + bb.x;
    o4[1] = gg.y * d1 * inv + bb.y;
    o4[2] = gg.z * d2 * inv + bb.z;
    o4[3] = gg.w * d3 * inv + bb.w;
    split_store_rm(out, R, lane, o4);
}

// ======================= GCN aggregate (fp16 gather) =======================
// SPLIT=1: relu -> split rows (OUT=128). SPLIT=0: relu -> f32 row-major.
template <int OUT, int SPLIT>
__global__ __launch_bounds__(256) void k_agg(const __half* __restrict__ supn,
                                             const float* __restrict__ selfm,
                                             const float* __restrict__ bias,
                                             void* __restrict__ out)
{
    const int V = OUT / 32;
    int node = blockIdx.x * 8 + (threadIdx.x >> 5);
    int lane = threadIdx.x & 31;

    float acc[V];
    {
        const float* sr = selfm + (size_t)node * OUT + lane * V;
        #pragma unroll
        for (int i = 0; i < V; i++) acc[i] = sr[i] + bias[lane * V + i];
    }

    int e0 = g_rowptr[node], e1 = g_rowptr[node + 1];
    for (int eb = e0; eb < e1; eb += 32) {
        int rem = e1 - eb;
        int c = 0; float wv = 0.f;
        if (lane < rem) { c = g_ecol[eb + lane]; wv = g_eval[eb + lane]; }
        if (rem >= 32) {
            #pragma unroll 8
            for (int j = 0; j < 32; j++) {
                int   cj = __shfl_sync(0xffffffffu, c, j);
                float wj = __shfl_sync(0xffffffffu, wv, j);
                const __half* srow = supn + (size_t)cj * OUT + lane * V;
                if (V == 4) {
                    uint2 u = *(const uint2*)srow;
                    float2 f0 = __half22float2(*(const __half2*)&u.x);
                    float2 f1 = __half22float2(*(const __half2*)&u.y);
                    acc[0] = fmaf(wj, f0.x, acc[0]);
                    acc[1] = fmaf(wj, f0.y, acc[1]);
                    acc[2] = fmaf(wj, f1.x, acc[2]);
                    acc[3] = fmaf(wj, f1.y, acc[3]);
                } else {
                    uint32_t u = *(const uint32_t*)srow;
                    float2 f0 = __half22float2(*(const __half2*)&u);
                    acc[0] = fmaf(wj, f0.x, acc[0]);
                    acc[1] = fmaf(wj, f0.y, acc[1]);
                }
            }
        } else {
            for (int j = 0; j < rem; j++) {
                int   cj = __shfl_sync(0xffffffffu, c, j);
                float wj = __shfl_sync(0xffffffffu, wv, j);
                const __half* srow = supn + (size_t)cj * OUT + lane * V;
                if (V == 4) {
                    uint2 u = *(const uint2*)srow;
                    float2 f0 = __half22float2(*(const __half2*)&u.x);
                    float2 f1 = __half22float2(*(const __half2*)&u.y);
                    acc[0] = fmaf(wj, f0.x, acc[0]);
                    acc[1] = fmaf(wj, f0.y, acc[1]);
                    acc[2] = fmaf(wj, f1.x, acc[2]);
                    acc[3] = fmaf(wj, f1.y, acc[3]);
                } else {
                    uint32_t u = *(const uint32_t*)srow;
                    float2 f0 = __half22float2(*(const __half2*)&u);
                    acc[0] = fmaf(wj, f0.x, acc[0]);
                    acc[1] = fmaf(wj, f0.y, acc[1]);
                }
            }
        }
    }

    if (SPLIT) {
        float v[4];
        #pragma unroll
        for (int i = 0; i < 4; i++) v[i] = fmaxf(acc[i], 0.f);
        split_store_rm((char*)out, node, lane, v);
    } else {
        float* orow = (float*)out + (size_t)node * OUT + lane * V;
        #pragma unroll
        for (int i = 0; i < V; i++) orow[i] = fmaxf(acc[i], 0.f);
    }
}

// ======================= launch =======================
extern "C" void kernel_launch(void* const* d_in, const int* in_sizes, int n_in,
                              void* d_out, int out_size)
{
    const float* x    = (const float*)d_in[0];
    const int*   er   = (const int*)d_in[1];
    const int*   ec   = (const int*)d_in[2];
    const float* ev   = (const float*)d_in[3];
    const float* fc1w = (const float*)d_in[4];
    const float* fc1b = (const float*)d_in[5];
    const float* fc2w = (const float*)d_in[6];
    const float* fc2b = (const float*)d_in[7];
    const float* lng  = (const float*)d_in[8];
    const float* lnb  = (const float*)d_in[9];
    const float *wn[4], *wsf[4], *gb[4];
    for (int i = 0; i < 4; i++) {
        wn[i]  = (const float*)d_in[10 + 3 * i];
        wsf[i] = (const float*)d_in[11 + 3 * i];
        gb[i]  = (const float*)d_in[12 + 3 * i];
    }
    float* outp = (float*)d_out;

    char *s0, *s1;
    float* selfb;
    __half* supn;
    __nv_bfloat16* wt;
    cudaGetSymbolAddress((void**)&s0,    g_h0);
    cudaGetSymbolAddress((void**)&s1,    g_h1);
    cudaGetSymbolAddress((void**)&supn,  g_supn);
    cudaGetSymbolAddress((void**)&selfb, g_self);
    cudaGetSymbolAddress((void**)&wt,    g_wt);
    auto WT = [&](int t) { return wt + (size_t)t * 32768; };

    cudaFuncSetAttribute(k_mm, cudaFuncAttributeMaxDynamicSharedMemorySize, A_BYTES);

    const int MT = (N_NODES + 127) / 128;   // 782

    k_wprep<<<dim3(128, 9), 128>>>(fc1w, fc2w, wn[0], wsf[0], wn[1], wsf[1],
                                   wn[2], wsf[2], wn[3], wsf[3], wt);            // 0
    k_xprep<<<NPAD / 8, 256>>>(x, s0);                                           // 1
    k_zero_rowptr<<<(NP1 + 255) / 256, 256>>>();                                 // 2
    k_mm<<<MT, 256, A_BYTES>>>(s0, WT(0), fc1b, s1, 0, nullptr, 0, 1);           // 3 <- profiled
    k_hist<<<(N_EDGES + 255) / 256, 256>>>(er);                                  // 4
    k_scan1<<<NSCAN_BLOCKS, 1024>>>();                                           // 5
    k_scan2<<<1, 1>>>();                                                         // 6
    k_scan3<<<NSCAN_BLOCKS, 1024>>>();                                           // 7
    k_fill<<<(N_EDGES + 255) / 256, 256>>>(er, ec, ev);                          // 8
    k_mm<<<MT, 256, A_BYTES>>>(s1, WT(1), fc2b, s0, 0, nullptr, 0, 1);           // 9
    k_ln<<<N_NODES / 8, 256>>>(s0, s1, lng, lnb);                                // 10

    char* cur = s1;
    char* nxt = s0;
    for (int l = 0; l < 3; l++) {
        k_mm<<<MT, 256, A_BYTES>>>(cur, WT(2 + 2 * l), nullptr, supn, 1, selfb, 2, 2);
        k_agg<128, 1><<<N_NODES / 8, 256>>>(supn, selfb, gb[l], nxt);
        char* t = cur; cur = nxt; nxt = t;
    }

    k_mm<<<MT, 256, A_BYTES>>>(cur, WT(8), nullptr, supn, 3, selfb, 3, 1);
    k_agg<64, 0><<<N_NODES / 8, 256>>>(supn, selfb, gb[3], outp);
}